// round 3
// baseline (speedup 1.0000x reference)
#include <cuda_runtime.h>
#include <math.h>

// Problem constants
#define BB 2
#define SS 1024
#define DD 2048
#define HH 16
#define DHH 128
#define DFF_ 8192
#define BS (BB*SS)          // 2048 rows
#define BH (BB*HH)          // 32 batched heads

// ---------------- scratch (device globals; no allocations allowed) ----------
__device__ float g_q[BH * SS * DHH];          // 16MB
__device__ float g_k[BH * SS * DHH];          // 16MB
__device__ float g_v[BH * SS * DHH];          // 16MB
__device__ float g_scores[(long)BH * SS * SS];// 128MB
__device__ float g_mha[BS * DD];              // 16MB  (concat-layout attn output)
__device__ float g_sum[BS * DD];              // 16MB  (residual + proj)
__device__ float g_x1[BS * DD];               // 16MB
__device__ float g_x2[BS * DD];               // 16MB
__device__ float g_ff[BS * DFF_];             // 64MB

// ---------------- generic tiled SGEMM: C = alpha*(A@B) + bias + res ---------
// A: [M,K], k-contiguous (stride lda per row).
// B: if BT==0: element(k,n) = B[k*ldb + n]  (n contiguous)
//    if BT==1: element(k,n) = B[n*ldb + k]  (k contiguous)  -> NT gemm
// C: element(m,n) = C[m*ldc + n]. Res (optional) shares C strides.
// batch z decomposed as zo = z/Hd, zi = z%Hd; per-operand offsets from (zo,zi).
template<int BT, int RELU>
__global__ __launch_bounds__(256, 2)
void gemm_k(const float* __restrict__ A, const float* __restrict__ B,
            const float* __restrict__ bias, const float* __restrict__ Res,
            float* __restrict__ C,
            int M, int N, int K, int lda, int ldb, int ldc,
            int Hd,
            long aS1, long aS2, long bS1, long bS2, long cS1, long cS2,
            long biasS2, float alpha)
{
    int z  = blockIdx.z;
    int zo = z / Hd, zi = z % Hd;
    A += zo * aS1 + zi * aS2;
    B += zo * bS1 + zi * bS2;
    long coff = zo * cS1 + zi * cS2;
    C += coff;
    if (Res)  Res  += coff;
    if (bias) bias += zi * biasS2;

    __shared__ float As[8][128];
    __shared__ float Bs[8][128];

    int tid = threadIdx.x;
    int bm  = blockIdx.y * 128;
    int bn  = blockIdx.x * 128;

    int tx = (tid & 15) * 8;   // col offset in tile
    int ty = (tid >> 4) * 8;   // row offset in tile

    float acc[8][8];
#pragma unroll
    for (int i = 0; i < 8; i++)
#pragma unroll
        for (int j = 0; j < 8; j++) acc[i][j] = 0.f;

    // A staging: 2 threads per row, float4 each (k-contiguous)
    int arow = tid >> 1;
    int akq  = (tid & 1) * 4;
    const float* Aptr = A + (long)(bm + arow) * lda + akq;

    // B staging pointers
    const float* Bptr;
    int bk = 0, bn4 = 0, bnr = 0, bkq = 0;
    if (BT) {
        bnr  = tid >> 1;           // n index within tile
        bkq  = (tid & 1) * 4;
        Bptr = B + (long)(bn + bnr) * ldb + bkq;
    } else {
        bk   = tid >> 5;           // k row 0..7
        bn4  = (tid & 31) * 4;     // n offset
        Bptr = B + (long)bk * ldb + bn + bn4;
    }

    for (int k0 = 0; k0 < K; k0 += 8) {
        float4 av = *(const float4*)Aptr;
        float4 bv = *(const float4*)Bptr;
        Aptr += 8;
        if (BT) Bptr += 8; else Bptr += 8 * (long)ldb;

        As[akq + 0][arow] = av.x;
        As[akq + 1][arow] = av.y;
        As[akq + 2][arow] = av.z;
        As[akq + 3][arow] = av.w;
        if (BT) {
            Bs[bkq + 0][bnr] = bv.x;
            Bs[bkq + 1][bnr] = bv.y;
            Bs[bkq + 2][bnr] = bv.z;
            Bs[bkq + 3][bnr] = bv.w;
        } else {
            *(float4*)&Bs[bk][bn4] = bv;
        }
        __syncthreads();

#pragma unroll
        for (int kk = 0; kk < 8; kk++) {
            float a0[8], b0[8];
            *(float4*)&a0[0] = *(float4*)&As[kk][ty];
            *(float4*)&a0[4] = *(float4*)&As[kk][ty + 4];
            *(float4*)&b0[0] = *(float4*)&Bs[kk][tx];
            *(float4*)&b0[4] = *(float4*)&Bs[kk][tx + 4];
#pragma unroll
            for (int i = 0; i < 8; i++)
#pragma unroll
                for (int j = 0; j < 8; j++)
                    acc[i][j] = fmaf(a0[i], b0[j], acc[i][j]);
        }
        __syncthreads();
    }

    // epilogue
#pragma unroll
    for (int i = 0; i < 8; i++) {
        long row = bm + ty + i;
        float* cp = C + row * ldc + bn + tx;
        const float* rp = Res ? (Res + row * ldc + bn + tx) : 0;
#pragma unroll
        for (int j = 0; j < 8; j += 4) {
            float4 o;
            float v0 = acc[i][j + 0] * alpha;
            float v1 = acc[i][j + 1] * alpha;
            float v2 = acc[i][j + 2] * alpha;
            float v3 = acc[i][j + 3] * alpha;
            if (bias) {
                const float* bp = bias + bn + tx + j;
                v0 += bp[0]; v1 += bp[1]; v2 += bp[2]; v3 += bp[3];
            }
            if (rp) {
                v0 += rp[j + 0]; v1 += rp[j + 1]; v2 += rp[j + 2]; v3 += rp[j + 3];
            }
            if (RELU) {
                v0 = fmaxf(v0, 0.f); v1 = fmaxf(v1, 0.f);
                v2 = fmaxf(v2, 0.f); v3 = fmaxf(v3, 0.f);
            }
            o.x = v0; o.y = v1; o.z = v2; o.w = v3;
            *(float4*)(cp + j) = o;
        }
    }
}

// ---------------- column softmax (normalize over q axis) --------------------
// scores layout [bh][q][k]; softmax over q for each fixed k.
// Online max/sum pass + one write pass (2 sweeps instead of 3).
__global__ void softmax_cols_k(float* __restrict__ sc)
{
    int col = blockIdx.x * 256 + threadIdx.x;
    float* base = sc + (long)blockIdx.y * SS * SS + col;
    float mx = -INFINITY, sum = 0.f;
    for (int q = 0; q < SS; q++) {
        float v = base[(long)q * SS];
        if (v > mx) {
            sum = sum * expf(mx - v) + 1.f;
            mx = v;
        } else {
            sum += expf(v - mx);
        }
    }
    float inv = 1.f / sum;
    for (int q = 0; q < SS; q++) {
        long idx = (long)q * SS;
        base[idx] = expf(base[idx] - mx) * inv;
    }
}

// ---------------- LayerNorm over last dim (D=2048) --------------------------
__device__ __forceinline__ float blockReduceSum(float val, float* sh)
{
    int tid = threadIdx.x;
#pragma unroll
    for (int o = 16; o; o >>= 1) val += __shfl_xor_sync(0xffffffffu, val, o);
    if ((tid & 31) == 0) sh[tid >> 5] = val;
    __syncthreads();
    if (tid < 8) {
        val = sh[tid];
#pragma unroll
        for (int o = 4; o; o >>= 1) val += __shfl_xor_sync(0xffu, val, o);
        if (tid == 0) sh[0] = val;
    }
    __syncthreads();
    float r = sh[0];
    __syncthreads();
    return r;
}

__global__ void layernorm_k(const float* __restrict__ x, const float* __restrict__ g,
                            const float* __restrict__ b, float* __restrict__ out)
{
    __shared__ float sh[8];
    long row = blockIdx.x;
    const float* xr = x + row * DD;
    int tid = threadIdx.x;
    float v[8];
#pragma unroll
    for (int i = 0; i < 8; i++) v[i] = xr[tid + i * 256];

    float local = 0.f;
#pragma unroll
    for (int i = 0; i < 8; i++) local += v[i];
    float mu = blockReduceSum(local, sh) * (1.f / DD);

    float local2 = 0.f;
#pragma unroll
    for (int i = 0; i < 8; i++) { float d = v[i] - mu; local2 += d * d; }
    float var = blockReduceSum(local2, sh) * (1.f / DD);
    float rstd = rsqrtf(var + 1e-5f);

    float* orow = out + row * DD;
#pragma unroll
    for (int i = 0; i < 8; i++) {
        int c = tid + i * 256;
        orow[c] = (v[i] - mu) * rstd * g[c] + b[c];
    }
}

// ---------------- host-side launch helpers ----------------------------------
static void launch_gemm(int BT, int RELU,
                        const float* A, const float* B, const float* bias,
                        const float* Res, float* C,
                        int M, int N, int K, int lda, int ldb, int ldc,
                        int batches, int Hd,
                        long aS1, long aS2, long bS1, long bS2,
                        long cS1, long cS2, long biasS2, float alpha)
{
    dim3 grid(N / 128, M / 128, batches), blk(256);
    if (BT)
        gemm_k<1, 0><<<grid, blk>>>(A, B, bias, Res, C, M, N, K, lda, ldb, ldc,
                                    Hd, aS1, aS2, bS1, bS2, cS1, cS2, biasS2, alpha);
    else if (RELU)
        gemm_k<0, 1><<<grid, blk>>>(A, B, bias, Res, C, M, N, K, lda, ldb, ldc,
                                    Hd, aS1, aS2, bS1, bS2, cS1, cS2, biasS2, alpha);
    else
        gemm_k<0, 0><<<grid, blk>>>(A, B, bias, Res, C, M, N, K, lda, ldb, ldc,
                                    Hd, aS1, aS2, bS1, bS2, cS1, cS2, biasS2, alpha);
}

extern "C" void kernel_launch(void* const* d_in, const int* in_sizes, int n_in,
                              void* d_out, int out_size)
{
    const float* x    = (const float*)d_in[0];
    const float* enc  = (const float*)d_in[1];
    const float* wq1  = (const float*)d_in[2];
    const float* wk1  = (const float*)d_in[3];
    const float* wv1  = (const float*)d_in[4];
    const float* bq1  = (const float*)d_in[5];
    const float* bk1  = (const float*)d_in[6];
    const float* bv1  = (const float*)d_in[7];
    const float* wp1  = (const float*)d_in[8];
    const float* bp1  = (const float*)d_in[9];
    const float* wq2  = (const float*)d_in[10];
    const float* wk2  = (const float*)d_in[11];
    const float* wv2  = (const float*)d_in[12];
    const float* bq2  = (const float*)d_in[13];
    const float* bk2  = (const float*)d_in[14];
    const float* bv2  = (const float*)d_in[15];
    const float* wp2  = (const float*)d_in[16];
    const float* bp2  = (const float*)d_in[17];
    const float* ln1g = (const float*)d_in[18];
    const float* ln1b = (const float*)d_in[19];
    const float* ln2g = (const float*)d_in[20];
    const float* ln2b = (const float*)d_in[21];
    const float* ln3g = (const float*)d_in[22];
    const float* ln3b = (const float*)d_in[23];
    const float* wf1  = (const float*)d_in[24];
    const float* bf1  = (const float*)d_in[25];
    const float* wf2  = (const float*)d_in[26];
    const float* bf2  = (const float*)d_in[27];
    float* out = (float*)d_out;

    float *q, *k, *v, *sc, *mha, *sum, *x1, *x2, *ff;
    cudaGetSymbolAddress((void**)&q,   g_q);
    cudaGetSymbolAddress((void**)&k,   g_k);
    cudaGetSymbolAddress((void**)&v,   g_v);
    cudaGetSymbolAddress((void**)&sc,  g_scores);
    cudaGetSymbolAddress((void**)&mha, g_mha);
    cudaGetSymbolAddress((void**)&sum, g_sum);
    cudaGetSymbolAddress((void**)&x1,  g_x1);
    cudaGetSymbolAddress((void**)&x2,  g_x2);
    cudaGetSymbolAddress((void**)&ff,  g_ff);

    const float scale = 0.08838834764831845f; // 1/sqrt(128)
    const long SD  = (long)SS * DD;     // per-batch row block in [B,S,D]
    const long SDH = (long)SS * DHH;    // per-head [S,DH] block
    const long WH  = (long)DD * DHH;    // per-head weight block
    const long S2  = (long)SS * SS;     // per-head score block

    // ============== attention block (shared for self & cross) ===============
    auto attn = [&](const float* qin, const float* kvin,
                    const float* wq, const float* wk, const float* wv,
                    const float* bq, const float* bk, const float* bv,
                    const float* wp, const float* bp,
                    const float* res)
    {
        // per-head projections: [S,D] @ [D,DH] for z = b*H + h
        launch_gemm(0, 0, qin,  wq, bq, 0, q, SS, DHH, DD, DD, DHH, DHH,
                    BH, HH, SD, 0, 0, WH, (long)HH * SDH, SDH, DHH, 1.f);
        launch_gemm(0, 0, kvin, wk, bk, 0, k, SS, DHH, DD, DD, DHH, DHH,
                    BH, HH, SD, 0, 0, WH, (long)HH * SDH, SDH, DHH, 1.f);
        launch_gemm(0, 0, kvin, wv, bv, 0, v, SS, DHH, DD, DD, DHH, DHH,
                    BH, HH, SD, 0, 0, WH, (long)HH * SDH, SDH, DHH, 1.f);
        // scores = q @ k^T * scale : NT gemm, [S,DH] x [S,DH]^T
        launch_gemm(1, 0, q, k, 0, 0, sc, SS, SS, DHH, DHH, DHH, SS,
                    BH, 1, SDH, 0, SDH, 0, S2, 0, 0, scale);
        // softmax over the q axis (columns)
        softmax_cols_k<<<dim3(SS / 256, BH), 256>>>(sc);
        // out = attn @ v, stored directly in concat layout [B,S,H*DH]
        launch_gemm(0, 0, sc, v, 0, 0, mha, SS, DHH, SS, SS, DHH, DD,
                    BH, HH, (long)HH * S2, S2, (long)HH * SDH, SDH,
                    SD, DHH, 0, 1.f);
        // proj + bias + residual
        launch_gemm(0, 0, mha, wp, bp, res, sum, BS, DD, DD, DD, DD, DD,
                    1, 1, 0, 0, 0, 0, 0, 0, 0, 1.f);
    };

    // ---- self attention + LN1 ----
    attn(x, x, wq1, wk1, wv1, bq1, bk1, bv1, wp1, bp1, x);
    layernorm_k<<<BS, 256>>>(sum, ln1g, ln1b, x1);

    // ---- cross attention (query=enc, kv=x1) + LN2 ----
    attn(enc, x1, wq2, wk2, wv2, bq2, bk2, bv2, wp2, bp2, x1);
    layernorm_k<<<BS, 256>>>(sum, ln2g, ln2b, x2);

    // ---- FFN + LN3 ----
    launch_gemm(0, 1, x2, wf1, bf1, 0, ff, BS, DFF_, DD, DD, DFF_, DFF_,
                1, 1, 0, 0, 0, 0, 0, 0, 0, 1.f);
    launch_gemm(0, 0, ff, wf2, bf2, x2, sum, BS, DD, DFF_, DFF_, DD, DD,
                1, 1, 0, 0, 0, 0, 0, 0, 0, 1.f);
    layernorm_k<<<BS, 256>>>(sum, ln3g, ln3b, out);

    (void)in_sizes; (void)n_in; (void)out_size;
}

// round 4
// speedup vs baseline: 1.0049x; 1.0049x over previous
#include <cuda_runtime.h>
#include <math.h>

// Problem constants
#define BB 2
#define SS 1024
#define DD 2048
#define HH 16
#define DHH 128
#define DFF_ 8192
#define BS (BB*SS)          // 2048 rows
#define BH (BB*HH)          // 32 batched heads

// ---------------- scratch (device globals; no allocations allowed) ----------
__device__ float g_q[BH * SS * DHH];          // 16MB
__device__ float g_k[BH * SS * DHH];          // 16MB
__device__ float g_v[BH * SS * DHH];          // 16MB
__device__ float g_scores[(long)BH * SS * SS];// 128MB
__device__ float g_mha[BS * DD];              // 16MB  (concat-layout attn output)
__device__ float g_sum[BS * DD];              // 16MB  (residual + proj)
__device__ float g_x1[BS * DD];               // 16MB
__device__ float g_x2[BS * DD];               // 16MB
__device__ float g_ff[BS * DFF_];             // 64MB

// ---------------- generic tiled SGEMM: C = alpha*(A@B) + bias + res ---------
// A: [M,K], k-contiguous (stride lda per row).
// B: if BT==0: element(k,n) = B[k*ldb + n]  (n contiguous)
//    if BT==1: element(k,n) = B[n*ldb + k]  (k contiguous)  -> NT gemm
// C: element(m,n) = C[m*ldc + n]. Res (optional) shares C strides.
// batch z decomposed as zo = z/Hd, zi = z%Hd; per-operand offsets from (zo,zi).
template<int BT, int RELU>
__global__ __launch_bounds__(256, 2)
void gemm_k(const float* __restrict__ A, const float* __restrict__ B,
            const float* __restrict__ bias, const float* __restrict__ Res,
            float* __restrict__ C,
            int M, int N, int K, int lda, int ldb, int ldc,
            int Hd,
            long aS1, long aS2, long bS1, long bS2, long cS1, long cS2,
            long biasS2, float alpha)
{
    int z  = blockIdx.z;
    int zo = z / Hd, zi = z % Hd;
    A += zo * aS1 + zi * aS2;
    B += zo * bS1 + zi * bS2;
    long coff = zo * cS1 + zi * cS2;
    C += coff;
    if (Res)  Res  += coff;
    if (bias) bias += zi * biasS2;

    __shared__ float As[8][128];
    __shared__ float Bs[8][128];

    int tid = threadIdx.x;
    int bm  = blockIdx.y * 128;
    int bn  = blockIdx.x * 128;

    int tx = (tid & 15) * 8;   // col offset in tile
    int ty = (tid >> 4) * 8;   // row offset in tile

    float acc[8][8];
#pragma unroll
    for (int i = 0; i < 8; i++)
#pragma unroll
        for (int j = 0; j < 8; j++) acc[i][j] = 0.f;

    // A staging: 2 threads per row, float4 each (k-contiguous)
    int arow = tid >> 1;
    int akq  = (tid & 1) * 4;
    const float* Aptr = A + (long)(bm + arow) * lda + akq;

    // B staging pointers
    const float* Bptr;
    int bk = 0, bn4 = 0, bnr = 0, bkq = 0;
    if (BT) {
        bnr  = tid >> 1;           // n index within tile
        bkq  = (tid & 1) * 4;
        Bptr = B + (long)(bn + bnr) * ldb + bkq;
    } else {
        bk   = tid >> 5;           // k row 0..7
        bn4  = (tid & 31) * 4;     // n offset
        Bptr = B + (long)bk * ldb + bn + bn4;
    }

    for (int k0 = 0; k0 < K; k0 += 8) {
        float4 av = *(const float4*)Aptr;
        float4 bv = *(const float4*)Bptr;
        Aptr += 8;
        if (BT) Bptr += 8; else Bptr += 8 * (long)ldb;

        As[akq + 0][arow] = av.x;
        As[akq + 1][arow] = av.y;
        As[akq + 2][arow] = av.z;
        As[akq + 3][arow] = av.w;
        if (BT) {
            Bs[bkq + 0][bnr] = bv.x;
            Bs[bkq + 1][bnr] = bv.y;
            Bs[bkq + 2][bnr] = bv.z;
            Bs[bkq + 3][bnr] = bv.w;
        } else {
            *(float4*)&Bs[bk][bn4] = bv;
        }
        __syncthreads();

#pragma unroll
        for (int kk = 0; kk < 8; kk++) {
            float a0[8], b0[8];
            *(float4*)&a0[0] = *(float4*)&As[kk][ty];
            *(float4*)&a0[4] = *(float4*)&As[kk][ty + 4];
            *(float4*)&b0[0] = *(float4*)&Bs[kk][tx];
            *(float4*)&b0[4] = *(float4*)&Bs[kk][tx + 4];
#pragma unroll
            for (int i = 0; i < 8; i++)
#pragma unroll
                for (int j = 0; j < 8; j++)
                    acc[i][j] = fmaf(a0[i], b0[j], acc[i][j]);
        }
        __syncthreads();
    }

    // epilogue
#pragma unroll
    for (int i = 0; i < 8; i++) {
        long row = bm + ty + i;
        float* cp = C + row * ldc + bn + tx;
        const float* rp = Res ? (Res + row * ldc + bn + tx) : 0;
#pragma unroll
        for (int j = 0; j < 8; j += 4) {
            float4 o;
            float v0 = acc[i][j + 0] * alpha;
            float v1 = acc[i][j + 1] * alpha;
            float v2 = acc[i][j + 2] * alpha;
            float v3 = acc[i][j + 3] * alpha;
            if (bias) {
                const float* bp = bias + bn + tx + j;
                v0 += bp[0]; v1 += bp[1]; v2 += bp[2]; v3 += bp[3];
            }
            if (rp) {
                v0 += rp[j + 0]; v1 += rp[j + 1]; v2 += rp[j + 2]; v3 += rp[j + 3];
            }
            if (RELU) {
                v0 = fmaxf(v0, 0.f); v1 = fmaxf(v1, 0.f);
                v2 = fmaxf(v2, 0.f); v3 = fmaxf(v3, 0.f);
            }
            o.x = v0; o.y = v1; o.z = v2; o.w = v3;
            *(float4*)(cp + j) = o;
        }
    }
}

// ---------------- column softmax (normalize over q axis) --------------------
// scores layout [bh][q][k]; softmax over q for each fixed k.
// Online max/sum pass + one write pass (2 sweeps instead of 3).
__global__ void softmax_cols_k(float* __restrict__ sc)
{
    int col = blockIdx.x * 256 + threadIdx.x;
    float* base = sc + (long)blockIdx.y * SS * SS + col;
    float mx = -INFINITY, sum = 0.f;
    for (int q = 0; q < SS; q++) {
        float v = base[(long)q * SS];
        if (v > mx) {
            sum = sum * expf(mx - v) + 1.f;
            mx = v;
        } else {
            sum += expf(v - mx);
        }
    }
    float inv = 1.f / sum;
    for (int q = 0; q < SS; q++) {
        long idx = (long)q * SS;
        base[idx] = expf(base[idx] - mx) * inv;
    }
}

// ---------------- LayerNorm over last dim (D=2048) --------------------------
__device__ __forceinline__ float blockReduceSum(float val, float* sh)
{
    int tid = threadIdx.x;
#pragma unroll
    for (int o = 16; o; o >>= 1) val += __shfl_xor_sync(0xffffffffu, val, o);
    if ((tid & 31) == 0) sh[tid >> 5] = val;
    __syncthreads();
    if (tid < 8) {
        val = sh[tid];
#pragma unroll
        for (int o = 4; o; o >>= 1) val += __shfl_xor_sync(0xffu, val, o);
        if (tid == 0) sh[0] = val;
    }
    __syncthreads();
    float r = sh[0];
    __syncthreads();
    return r;
}

__global__ void layernorm_k(const float* __restrict__ x, const float* __restrict__ g,
                            const float* __restrict__ b, float* __restrict__ out)
{
    __shared__ float sh[8];
    long row = blockIdx.x;
    const float* xr = x + row * DD;
    int tid = threadIdx.x;
    float v[8];
#pragma unroll
    for (int i = 0; i < 8; i++) v[i] = xr[tid + i * 256];

    float local = 0.f;
#pragma unroll
    for (int i = 0; i < 8; i++) local += v[i];
    float mu = blockReduceSum(local, sh) * (1.f / DD);

    float local2 = 0.f;
#pragma unroll
    for (int i = 0; i < 8; i++) { float d = v[i] - mu; local2 += d * d; }
    float var = blockReduceSum(local2, sh) * (1.f / DD);
    float rstd = rsqrtf(var + 1e-5f);

    float* orow = out + row * DD;
#pragma unroll
    for (int i = 0; i < 8; i++) {
        int c = tid + i * 256;
        orow[c] = (v[i] - mu) * rstd * g[c] + b[c];
    }
}

// ---------------- host-side launch helpers ----------------------------------
static void launch_gemm(int BT, int RELU,
                        const float* A, const float* B, const float* bias,
                        const float* Res, float* C,
                        int M, int N, int K, int lda, int ldb, int ldc,
                        int batches, int Hd,
                        long aS1, long aS2, long bS1, long bS2,
                        long cS1, long cS2, long biasS2, float alpha)
{
    dim3 grid(N / 128, M / 128, batches), blk(256);
    if (BT)
        gemm_k<1, 0><<<grid, blk>>>(A, B, bias, Res, C, M, N, K, lda, ldb, ldc,
                                    Hd, aS1, aS2, bS1, bS2, cS1, cS2, biasS2, alpha);
    else if (RELU)
        gemm_k<0, 1><<<grid, blk>>>(A, B, bias, Res, C, M, N, K, lda, ldb, ldc,
                                    Hd, aS1, aS2, bS1, bS2, cS1, cS2, biasS2, alpha);
    else
        gemm_k<0, 0><<<grid, blk>>>(A, B, bias, Res, C, M, N, K, lda, ldb, ldc,
                                    Hd, aS1, aS2, bS1, bS2, cS1, cS2, biasS2, alpha);
}

extern "C" void kernel_launch(void* const* d_in, const int* in_sizes, int n_in,
                              void* d_out, int out_size)
{
    const float* x    = (const float*)d_in[0];
    const float* enc  = (const float*)d_in[1];
    const float* wq1  = (const float*)d_in[2];
    const float* wk1  = (const float*)d_in[3];
    const float* wv1  = (const float*)d_in[4];
    const float* bq1  = (const float*)d_in[5];
    const float* bk1  = (const float*)d_in[6];
    const float* bv1  = (const float*)d_in[7];
    const float* wp1  = (const float*)d_in[8];
    const float* bp1  = (const float*)d_in[9];
    const float* wq2  = (const float*)d_in[10];
    const float* wk2  = (const float*)d_in[11];
    const float* wv2  = (const float*)d_in[12];
    const float* bq2  = (const float*)d_in[13];
    const float* bk2  = (const float*)d_in[14];
    const float* bv2  = (const float*)d_in[15];
    const float* wp2  = (const float*)d_in[16];
    const float* bp2  = (const float*)d_in[17];
    const float* ln1g = (const float*)d_in[18];
    const float* ln1b = (const float*)d_in[19];
    const float* ln2g = (const float*)d_in[20];
    const float* ln2b = (const float*)d_in[21];
    const float* ln3g = (const float*)d_in[22];
    const float* ln3b = (const float*)d_in[23];
    const float* wf1  = (const float*)d_in[24];
    const float* bf1  = (const float*)d_in[25];
    const float* wf2  = (const float*)d_in[26];
    const float* bf2  = (const float*)d_in[27];
    float* out = (float*)d_out;

    float *q, *k, *v, *sc, *mha, *sum, *x1, *x2, *ff;
    cudaGetSymbolAddress((void**)&q,   g_q);
    cudaGetSymbolAddress((void**)&k,   g_k);
    cudaGetSymbolAddress((void**)&v,   g_v);
    cudaGetSymbolAddress((void**)&sc,  g_scores);
    cudaGetSymbolAddress((void**)&mha, g_mha);
    cudaGetSymbolAddress((void**)&sum, g_sum);
    cudaGetSymbolAddress((void**)&x1,  g_x1);
    cudaGetSymbolAddress((void**)&x2,  g_x2);
    cudaGetSymbolAddress((void**)&ff,  g_ff);

    const float scale = 0.08838834764831845f; // 1/sqrt(128)
    const long SD  = (long)SS * DD;     // per-batch row block in [B,S,D]
    const long SDH = (long)SS * DHH;    // per-head [S,DH] block
    const long WH  = (long)DD * DHH;    // per-head weight block
    const long S2  = (long)SS * SS;     // per-head score block

    // ============== attention block (shared for self & cross) ===============
    auto attn = [&](const float* qin, const float* kvin,
                    const float* wq, const float* wk, const float* wv,
                    const float* bq, const float* bk, const float* bv,
                    const float* wp, const float* bp,
                    const float* res)
    {
        // per-head projections: [S,D] @ [D,DH] for z = b*H + h
        launch_gemm(0, 0, qin,  wq, bq, 0, q, SS, DHH, DD, DD, DHH, DHH,
                    BH, HH, SD, 0, 0, WH, (long)HH * SDH, SDH, DHH, 1.f);
        launch_gemm(0, 0, kvin, wk, bk, 0, k, SS, DHH, DD, DD, DHH, DHH,
                    BH, HH, SD, 0, 0, WH, (long)HH * SDH, SDH, DHH, 1.f);
        launch_gemm(0, 0, kvin, wv, bv, 0, v, SS, DHH, DD, DD, DHH, DHH,
                    BH, HH, SD, 0, 0, WH, (long)HH * SDH, SDH, DHH, 1.f);
        // scores = q @ k^T * scale : NT gemm, [S,DH] x [S,DH]^T
        launch_gemm(1, 0, q, k, 0, 0, sc, SS, SS, DHH, DHH, DHH, SS,
                    BH, 1, SDH, 0, SDH, 0, S2, 0, 0, scale);
        // softmax over the q axis (columns)
        softmax_cols_k<<<dim3(SS / 256, BH), 256>>>(sc);
        // out = attn @ v, stored directly in concat layout [B,S,H*DH]
        launch_gemm(0, 0, sc, v, 0, 0, mha, SS, DHH, SS, SS, DHH, DD,
                    BH, HH, (long)HH * S2, S2, (long)HH * SDH, SDH,
                    SD, DHH, 0, 1.f);
        // proj + bias + residual
        launch_gemm(0, 0, mha, wp, bp, res, sum, BS, DD, DD, DD, DD, DD,
                    1, 1, 0, 0, 0, 0, 0, 0, 0, 1.f);
    };

    // ---- self attention + LN1 ----
    attn(x, x, wq1, wk1, wv1, bq1, bk1, bv1, wp1, bp1, x);
    layernorm_k<<<BS, 256>>>(sum, ln1g, ln1b, x1);

    // ---- cross attention (query=enc, kv=x1) + LN2 ----
    attn(enc, x1, wq2, wk2, wv2, bq2, bk2, bv2, wp2, bp2, x1);
    layernorm_k<<<BS, 256>>>(sum, ln2g, ln2b, x2);

    // ---- FFN + LN3 ----
    launch_gemm(0, 1, x2, wf1, bf1, 0, ff, BS, DFF_, DD, DD, DFF_, DFF_,
                1, 1, 0, 0, 0, 0, 0, 0, 0, 1.f);
    launch_gemm(0, 0, ff, wf2, bf2, x2, sum, BS, DD, DFF_, DFF_, DD, DD,
                1, 1, 0, 0, 0, 0, 0, 0, 0, 1.f);
    layernorm_k<<<BS, 256>>>(sum, ln3g, ln3b, out);

    (void)in_sizes; (void)n_in; (void)out_size;
}

// round 14
// speedup vs baseline: 2.1787x; 2.1682x over previous
#include <cuda_runtime.h>
#include <cuda_bf16.h>
#include <math.h>
#include <stdint.h>

typedef __nv_bfloat16 bf16;

#define S_ 1024
#define D_ 2048
#define H_ 16
#define DH_ 128
#define DFF 8192
#define BS_ 2048
#define BH_ 32
#define MB4 4194304L

// ---------------- scratch ----------------
__device__ float g_sc[(long)BH_*S_*S_];   // 128MB fp32 scores
__device__ float g_sum[(long)BS_*D_];
__device__ float g_x1f[(long)BS_*D_];
__device__ float g_x2f[(long)BS_*D_];
__device__ bf16  g_wh[16*MB4];            // split weights (transposed)
__device__ bf16  g_wl[16*MB4];
__device__ bf16  g_ah[20*MB4];            // split activations
__device__ bf16  g_al[20*MB4];

#define OW_Q1 0L
#define OW_K1 (1*MB4)
#define OW_V1 (2*MB4)
#define OW_P1 (3*MB4)
#define OW_Q2 (4*MB4)
#define OW_K2 (5*MB4)
#define OW_V2 (6*MB4)
#define OW_P2 (7*MB4)
#define OW_F1 (8*MB4)
#define OW_F2 (12*MB4)
#define OA_X  0L
#define OA_E  (1*MB4)
#define OA_Q  (2*MB4)
#define OA_K  (3*MB4)
#define OA_VT (4*MB4)
#define OA_M  (5*MB4)
#define OA_X1 (6*MB4)
#define OA_X2 (7*MB4)
#define OA_P  (8*MB4)
#define OA_FF (16*MB4)

// ---------------- helpers ----------------
__device__ __forceinline__ uint32_t s2u(const void* p){
    uint32_t a; asm("{ .reg .u64 t; cvta.to.shared.u64 t,%1; cvt.u32.u64 %0,t; }":"=r"(a):"l"(p)); return a;
}
#define SW128(x) ((x)^(((x)>>3)&0x70))
__device__ __forceinline__ void cpa16(uint32_t d,const void* s){
    asm volatile("cp.async.cg.shared.global [%0],[%1],16;"::"r"(d),"l"(s):"memory");
}
__device__ __forceinline__ uint32_t pkb(bf16 a,bf16 b){
    unsigned short x=*(unsigned short*)&a, y=*(unsigned short*)&b;
    return (uint32_t)x|((uint32_t)y<<16);
}

// ============================================================================
// HMMA split-bf16 NT GEMM via mma.sync m16n8k16 (portable sm_80+ path).
// Tile 128x128, 8 warps (2m x 4n), warp tile 64x32, K slab 64, double buffer.
// C[m,n] = alpha*sum_k(Ah.Bh + Al.Bh + Ah.Bl)  (+bias +Res, opt relu).
// OSPLIT: write bf16 hi/lo pair instead of fp32.
// ============================================================================
template<int RELU,int OSPLIT,int RBIAS>
__global__ void __launch_bounds__(256)
gemm_t(const bf16* __restrict__ Ahi,const bf16* __restrict__ Alo,
       const bf16* __restrict__ Bhi,const bf16* __restrict__ Blo,
       const float* __restrict__ bias,const float* __restrict__ Res,
       float* __restrict__ C,bf16* __restrict__ Chi,bf16* __restrict__ Clo,
       int Kseg,int ldc,int Hd,
       long aS1,long aS2,long bS1,long bS2,long cS1,long cS2,long biasS2,float alpha)
{
    extern __shared__ char smem[];
    uint32_t sb=s2u(smem);
    const int ABYTES=16384;   // 128 rows x 64 bf16

    int tid=threadIdx.x, wid=tid>>5, lane=tid&31;
    int z=blockIdx.z, zo=z/Hd, zi=z-zo*Hd;
    const char* Ah=(const char*)(Ahi+zo*aS1+zi*aS2);
    const char* Al=(const char*)(Alo+zo*aS1+zi*aS2);
    const char* Bh=(const char*)(Bhi+zo*bS1+zi*bS2);
    const char* Bl=(const char*)(Blo+zo*bS1+zi*bS2);
    long coff=zo*cS1+zi*cS2;
    if(bias) bias+=zi*biasS2;

    long bm=(long)blockIdx.y*128, bn=(long)blockIdx.x*128;
    long rowb=(long)Kseg*2;
    int wm=(wid&1)*64, wn=(wid>>1)*32;

    int sps=Kseg>>6, nslab=3*sps;

    float acc[4][4][4];
    #pragma unroll
    for(int i=0;i<4;i++)
    #pragma unroll
    for(int j2=0;j2<4;j2++)
    #pragma unroll
    for(int k2=0;k2<4;k2++) acc[i][j2][k2]=0.f;

    auto load_slab=[&](int s,int j){
        int seg=s/sps;
        long k0=(long)(s-seg*sps)*128;   // byte offset (64 bf16)
        const char* Ap=((seg==1)?Al:Ah)+bm*rowb+k0;
        const char* Bp=((seg==2)?Bl:Bh)+bn*rowb+k0;
        uint32_t ab=sb+j*ABYTES, bb=sb+2*ABYTES+j*ABYTES;
        #pragma unroll
        for(int c=0;c<4;c++){
            int cc=tid+c*256, row=cc>>3, o=(cc&7)*16;
            cpa16(ab+SW128(row*128+o), Ap+(long)row*rowb+o);
        }
        #pragma unroll
        for(int c=0;c<4;c++){
            int cc=tid+c*256, row=cc>>3, o=(cc&7)*16;
            cpa16(bb+SW128(row*128+o), Bp+(long)row*rowb+o);
        }
        asm volatile("cp.async.commit_group;":::"memory");
    };

    // ldmatrix addressing (per-lane, constant across slabs)
    int arow=(lane&7)|(((lane>>3)&1)<<3);   // m-row within 16
    int acol=(lane>>4)*16;                  // k-half byte offset
    int brow=lane&7;                        // n-row within 8
    int bcol=((lane>>3)&1)*16;              // k-half byte offset

    load_slab(0,0);
    for(int s=0;s<nslab;s++){
        int b=s&1;
        if(s+1<nslab){
            load_slab(s+1,(s+1)&1);
            asm volatile("cp.async.wait_group 1;":::"memory");
        } else {
            asm volatile("cp.async.wait_group 0;":::"memory");
        }
        __syncthreads();

        uint32_t ab=sb+b*ABYTES, bb=sb+2*ABYTES+b*ABYTES;
        #pragma unroll
        for(int ks=0;ks<4;ks++){
            int kb=ks*32;  // byte offset of k16 step
            uint32_t a[4][4], bf[4][2];
            #pragma unroll
            for(int mt=0;mt<4;mt++){
                uint32_t off=(uint32_t)(wm+mt*16+arow)*128 + kb + acol;
                uint32_t ad=ab+SW128(off);
                asm volatile("ldmatrix.sync.aligned.m8n8.x4.shared.b16 {%0,%1,%2,%3},[%4];"
                    :"=r"(a[mt][0]),"=r"(a[mt][1]),"=r"(a[mt][2]),"=r"(a[mt][3]):"r"(ad));
            }
            #pragma unroll
            for(int nt=0;nt<4;nt++){
                uint32_t off=(uint32_t)(wn+nt*8+brow)*128 + kb + bcol;
                uint32_t bd=bb+SW128(off);
                asm volatile("ldmatrix.sync.aligned.m8n8.x2.shared.b16 {%0,%1},[%2];"
                    :"=r"(bf[nt][0]),"=r"(bf[nt][1]):"r"(bd));
            }
            #pragma unroll
            for(int mt=0;mt<4;mt++)
            #pragma unroll
            for(int nt=0;nt<4;nt++)
                asm volatile("mma.sync.aligned.m16n8k16.row.col.f32.bf16.bf16.f32 "
                    "{%0,%1,%2,%3},{%4,%5,%6,%7},{%8,%9},{%0,%1,%2,%3};"
                    :"+f"(acc[mt][nt][0]),"+f"(acc[mt][nt][1]),
                     "+f"(acc[mt][nt][2]),"+f"(acc[mt][nt][3])
                    :"r"(a[mt][0]),"r"(a[mt][1]),"r"(a[mt][2]),"r"(a[mt][3]),
                     "r"(bf[nt][0]),"r"(bf[nt][1]));
        }
        __syncthreads();
    }

    // epilogue: d0,d1 = row g cols 2j,2j+1; d2,d3 = row g+8
    int g=lane>>2, j=lane&3;
    #pragma unroll
    for(int mt=0;mt<4;mt++){
        #pragma unroll
        for(int h=0;h<2;h++){
            long mrow=bm+wm+mt*16+g+h*8;
            long crow=coff+mrow*(long)ldc+bn;
            float rbv=0.f;
            if(RBIAS){ if(bias) rbv=__ldg(bias+mrow); }
            #pragma unroll
            for(int nt=0;nt<4;nt++){
                int col=wn+nt*8+j*2;
                float v0=acc[mt][nt][h*2+0]*alpha;
                float v1=acc[mt][nt][h*2+1]*alpha;
                if(RBIAS){ v0+=rbv; v1+=rbv; }
                else if(bias){ v0+=__ldg(bias+bn+col); v1+=__ldg(bias+bn+col+1); }
                if(Res){
                    float2 rv=*(const float2*)(Res+crow+col);
                    v0+=rv.x; v1+=rv.y;
                }
                if(RELU){ v0=fmaxf(v0,0.f); v1=fmaxf(v1,0.f); }
                if(OSPLIT){
                    bf16 h0=__float2bfloat16(v0), h1=__float2bfloat16(v1);
                    *(uint32_t*)(Chi+crow+col)=pkb(h0,h1);
                    *(uint32_t*)(Clo+crow+col)=pkb(
                        __float2bfloat16(v0-__bfloat162float(h0)),
                        __float2bfloat16(v1-__bfloat162float(h1)));
                } else {
                    *(float2*)(C+crow+col)=make_float2(v0,v1);
                }
            }
        }
    }
}

// ---------------- split fp32 -> bf16 hi/lo ----------------
__global__ void k_split(const float* __restrict__ in,bf16* __restrict__ oh,
                        bf16* __restrict__ ol,long n){
    long i=((long)blockIdx.x*256+threadIdx.x)*4;
    if(i>=n) return;
    float4 v=*(const float4*)(in+i);
    bf16 h0=__float2bfloat16(v.x),h1=__float2bfloat16(v.y);
    bf16 h2=__float2bfloat16(v.z),h3=__float2bfloat16(v.w);
    *(uint2*)(oh+i)=make_uint2(pkb(h0,h1),pkb(h2,h3));
    *(uint2*)(ol+i)=make_uint2(
        pkb(__float2bfloat16(v.x-__bfloat162float(h0)),__float2bfloat16(v.y-__bfloat162float(h1))),
        pkb(__float2bfloat16(v.z-__bfloat162float(h2)),__float2bfloat16(v.w-__bfloat162float(h3))));
}

// ---------------- split + transpose: in[z][R][C] -> out[z][C][R] ----------------
__global__ void k_splitT(const float* __restrict__ in,bf16* __restrict__ oh,
                         bf16* __restrict__ ol,int R,int C,long zin,long zout){
    __shared__ float t[32][33];
    in+=(long)blockIdx.z*zin;
    long ob=(long)blockIdx.z*zout;
    int c0=blockIdx.x*32, r0=blockIdx.y*32;
    int tx=threadIdx.x, ty=threadIdx.y;
    #pragma unroll
    for(int i=0;i<32;i+=8) t[ty+i][tx]=in[(long)(r0+ty+i)*C+c0+tx];
    __syncthreads();
    #pragma unroll
    for(int i=0;i<32;i+=8){
        float v=t[tx][ty+i];
        bf16 h=__float2bfloat16(v);
        long o=ob+(long)(c0+ty+i)*R+r0+tx;
        oh[o]=h; ol[o]=__float2bfloat16(v-__bfloat162float(h));
    }
}

// ---------------- column softmax (over q) + split write ----------------
__global__ void k_softmax(const float* __restrict__ sc,bf16* __restrict__ ph,
                          bf16* __restrict__ pl){
    int col=blockIdx.x*256+threadIdx.x;
    long zb=(long)blockIdx.y*S_*S_;
    const float* base=sc+zb+col;
    float mx=-INFINITY,sum=0.f;
    for(int q=0;q<S_;q++){
        float v=base[(long)q*S_];
        if(v>mx){ sum=sum*expf(mx-v)+1.f; mx=v; } else sum+=expf(v-mx);
    }
    float inv=1.f/sum;
    for(int q=0;q<S_;q++){
        float p=expf(base[(long)q*S_]-mx)*inv;
        bf16 h=__float2bfloat16(p);
        long o=zb+(long)q*S_+col;
        ph[o]=h; pl[o]=__float2bfloat16(p-__bfloat162float(h));
    }
}

// ---------------- LayerNorm (+ optional split) ----------------
__device__ __forceinline__ float brsum(float val,float* sh){
    int tid=threadIdx.x;
    #pragma unroll
    for(int o=16;o;o>>=1) val+=__shfl_xor_sync(0xffffffffu,val,o);
    if((tid&31)==0) sh[tid>>5]=val;
    __syncthreads();
    if(tid<8){ val=sh[tid];
        #pragma unroll
        for(int o=4;o;o>>=1) val+=__shfl_xor_sync(0xffu,val,o);
        if(tid==0) sh[0]=val; }
    __syncthreads();
    float r=sh[0]; __syncthreads(); return r;
}
template<int OSPLIT>
__global__ void ln_k(const float* __restrict__ x,const float* __restrict__ g,
                     const float* __restrict__ b,float* __restrict__ out,
                     bf16* __restrict__ oh,bf16* __restrict__ ol){
    __shared__ float sh[8];
    long row=blockIdx.x;
    const float* xr=x+row*D_;
    int tid=threadIdx.x;
    float v[8];
    #pragma unroll
    for(int i=0;i<8;i++) v[i]=xr[tid+i*256];
    float lc=0.f;
    #pragma unroll
    for(int i=0;i<8;i++) lc+=v[i];
    float mu=brsum(lc,sh)*(1.f/D_);
    float l2=0.f;
    #pragma unroll
    for(int i=0;i<8;i++){ float d=v[i]-mu; l2+=d*d; }
    float rstd=rsqrtf(brsum(l2,sh)*(1.f/D_)+1e-5f);
    #pragma unroll
    for(int i=0;i<8;i++){
        int c=tid+i*256;
        float o=(v[i]-mu)*rstd*g[c]+b[c];
        out[row*D_+c]=o;
        if(OSPLIT){
            bf16 h=__float2bfloat16(o);
            oh[row*D_+c]=h; ol[row*D_+c]=__float2bfloat16(o-__bfloat162float(h));
        }
    }
}

// ---------------- host ----------------
#define SMSZ 65536

extern "C" void kernel_launch(void* const* d_in,const int* in_sizes,int n_in,
                              void* d_out,int out_size)
{
    const float* x   =(const float*)d_in[0];
    const float* enc =(const float*)d_in[1];
    const float* wq1 =(const float*)d_in[2];
    const float* wk1 =(const float*)d_in[3];
    const float* wv1 =(const float*)d_in[4];
    const float* bq1 =(const float*)d_in[5];
    const float* bk1 =(const float*)d_in[6];
    const float* bv1 =(const float*)d_in[7];
    const float* wp1 =(const float*)d_in[8];
    const float* bp1 =(const float*)d_in[9];
    const float* wq2 =(const float*)d_in[10];
    const float* wk2 =(const float*)d_in[11];
    const float* wv2 =(const float*)d_in[12];
    const float* bq2 =(const float*)d_in[13];
    const float* bk2 =(const float*)d_in[14];
    const float* bv2 =(const float*)d_in[15];
    const float* wp2 =(const float*)d_in[16];
    const float* bp2 =(const float*)d_in[17];
    const float* ln1g=(const float*)d_in[18];
    const float* ln1b=(const float*)d_in[19];
    const float* ln2g=(const float*)d_in[20];
    const float* ln2b=(const float*)d_in[21];
    const float* ln3g=(const float*)d_in[22];
    const float* ln3b=(const float*)d_in[23];
    const float* wf1 =(const float*)d_in[24];
    const float* bf1 =(const float*)d_in[25];
    const float* wf2 =(const float*)d_in[26];
    const float* bf2 =(const float*)d_in[27];
    float* out=(float*)d_out;

    float *sc,*sum,*x1f,*x2f; bf16 *wh,*wl,*ah,*al;
    cudaGetSymbolAddress((void**)&sc,g_sc);
    cudaGetSymbolAddress((void**)&sum,g_sum);
    cudaGetSymbolAddress((void**)&x1f,g_x1f);
    cudaGetSymbolAddress((void**)&x2f,g_x2f);
    cudaGetSymbolAddress((void**)&wh,g_wh);
    cudaGetSymbolAddress((void**)&wl,g_wl);
    cudaGetSymbolAddress((void**)&ah,g_ah);
    cudaGetSymbolAddress((void**)&al,g_al);

    cudaFuncSetAttribute(gemm_t<0,1,0>,cudaFuncAttributeMaxDynamicSharedMemorySize,SMSZ);
    cudaFuncSetAttribute(gemm_t<0,1,1>,cudaFuncAttributeMaxDynamicSharedMemorySize,SMSZ);
    cudaFuncSetAttribute(gemm_t<0,0,0>,cudaFuncAttributeMaxDynamicSharedMemorySize,SMSZ);
    cudaFuncSetAttribute(gemm_t<1,1,0>,cudaFuncAttributeMaxDynamicSharedMemorySize,SMSZ);

    dim3 tb(32,8);
    // weight split+transpose
    k_splitT<<<dim3(4,64,H_),tb>>>(wq1,wh+OW_Q1,wl+OW_Q1,D_,DH_,(long)D_*DH_,(long)DH_*D_);
    k_splitT<<<dim3(4,64,H_),tb>>>(wk1,wh+OW_K1,wl+OW_K1,D_,DH_,(long)D_*DH_,(long)DH_*D_);
    k_splitT<<<dim3(4,64,H_),tb>>>(wv1,wh+OW_V1,wl+OW_V1,D_,DH_,(long)D_*DH_,(long)DH_*D_);
    k_splitT<<<dim3(64,64,1),tb>>>(wp1,wh+OW_P1,wl+OW_P1,D_,D_,0L,0L);
    k_splitT<<<dim3(4,64,H_),tb>>>(wq2,wh+OW_Q2,wl+OW_Q2,D_,DH_,(long)D_*DH_,(long)DH_*D_);
    k_splitT<<<dim3(4,64,H_),tb>>>(wk2,wh+OW_K2,wl+OW_K2,D_,DH_,(long)D_*DH_,(long)DH_*D_);
    k_splitT<<<dim3(4,64,H_),tb>>>(wv2,wh+OW_V2,wl+OW_V2,D_,DH_,(long)D_*DH_,(long)DH_*D_);
    k_splitT<<<dim3(64,64,1),tb>>>(wp2,wh+OW_P2,wl+OW_P2,D_,D_,0L,0L);
    k_splitT<<<dim3(256,64,1),tb>>>(wf1,wh+OW_F1,wl+OW_F1,D_,DFF,0L,0L);
    k_splitT<<<dim3(64,256,1),tb>>>(wf2,wh+OW_F2,wl+OW_F2,DFF,D_,0L,0L);
    // input splits
    k_split<<<4096,256>>>(x,  ah+OA_X,al+OA_X,(long)BS_*D_);
    k_split<<<4096,256>>>(enc,ah+OA_E,al+OA_E,(long)BS_*D_);

    const float scale=0.08838834764831845f;

    auto attn=[&](long qoff,long kvoff,long owq,long owk,long owv,long owp,
                  const float* bq,const float* bk,const float* bv,const float* bp,
                  const float* res){
        // Q proj: A=acts[S,D], B=WqT[DH,D]
        gemm_t<0,1,0><<<dim3(1,8,32),256,SMSZ>>>(ah+qoff,al+qoff,wh+owq,wl+owq,bq,0,0,
            ah+OA_Q,al+OA_Q, D_,DH_,H_, (long)S_*D_,0L, 0L,(long)DH_*D_,
            (long)H_*S_*DH_,(long)S_*DH_, DH_,1.f);
        // K proj
        gemm_t<0,1,0><<<dim3(1,8,32),256,SMSZ>>>(ah+kvoff,al+kvoff,wh+owk,wl+owk,bk,0,0,
            ah+OA_K,al+OA_K, D_,DH_,H_, (long)S_*D_,0L, 0L,(long)DH_*D_,
            (long)H_*S_*DH_,(long)S_*DH_, DH_,1.f);
        // V^T proj: A=WvT[DH,D], B=acts[S,D] -> VT[bh][DH][S], row bias
        gemm_t<0,1,1><<<dim3(8,1,32),256,SMSZ>>>(wh+owv,wl+owv,ah+kvoff,al+kvoff,bv,0,0,
            ah+OA_VT,al+OA_VT, D_,S_,H_, 0L,(long)DH_*D_, (long)S_*D_,0L,
            (long)H_*DH_*S_,(long)DH_*S_, DH_,1.f);
        // scores = scale * Q K^T (fp32 out)
        gemm_t<0,0,0><<<dim3(8,8,32),256,SMSZ>>>(ah+OA_Q,al+OA_Q,ah+OA_K,al+OA_K,0,0,sc,0,0,
            DH_,S_,1, (long)S_*DH_,0L, (long)S_*DH_,0L, (long)S_*S_,0L, 0L,scale);
        // softmax over q + split
        k_softmax<<<dim3(4,32),256>>>(sc,ah+OA_P,al+OA_P);
        // mha = P @ V (A=P[S,S], B=VT[DH,S]) -> concat layout split
        gemm_t<0,1,0><<<dim3(1,8,32),256,SMSZ>>>(ah+OA_P,al+OA_P,ah+OA_VT,al+OA_VT,0,0,0,
            ah+OA_M,al+OA_M, S_,D_,H_, (long)H_*S_*S_,(long)S_*S_,
            (long)H_*DH_*S_,(long)DH_*S_, (long)S_*D_,(long)DH_, 0L,1.f);
        // out proj + bias + residual -> sum (fp32)
        gemm_t<0,0,0><<<dim3(16,16,1),256,SMSZ>>>(ah+OA_M,al+OA_M,wh+owp,wl+owp,bp,res,sum,0,0,
            D_,D_,1, 0L,0L,0L,0L,0L,0L, 0L,1.f);
    };

    // self attention + LN1 (res = x)
    attn(OA_X,OA_X,OW_Q1,OW_K1,OW_V1,OW_P1,bq1,bk1,bv1,bp1,x);
    ln_k<1><<<BS_,256>>>(sum,ln1g,ln1b,x1f,ah+OA_X1,al+OA_X1);
    // cross attention (q=enc, kv=x1) + LN2 (res = x1)
    attn(OA_E,OA_X1,OW_Q2,OW_K2,OW_V2,OW_P2,bq2,bk2,bv2,bp2,x1f);
    ln_k<1><<<BS_,256>>>(sum,ln2g,ln2b,x2f,ah+OA_X2,al+OA_X2);
    // FFN
    gemm_t<1,1,0><<<dim3(64,16,1),256,SMSZ>>>(ah+OA_X2,al+OA_X2,wh+OW_F1,wl+OW_F1,bf1,0,0,
        ah+OA_FF,al+OA_FF, D_,DFF,1, 0L,0L,0L,0L,0L,0L, 0L,1.f);
    gemm_t<0,0,0><<<dim3(16,16,1),256,SMSZ>>>(ah+OA_FF,al+OA_FF,wh+OW_F2,wl+OW_F2,bf2,x2f,sum,0,0,
        DFF,D_,1, 0L,0L,0L,0L,0L,0L, 0L,1.f);
    ln_k<0><<<BS_,256>>>(sum,ln3g,ln3b,out,0,0);

    (void)in_sizes;(void)n_in;(void)out_size;
}